// round 1
// baseline (speedup 1.0000x reference)
#include <cuda_runtime.h>

#define T_STEPS 20
#define N_NODES 50000
#define K_ACT   10000
#define RNN     128
#define EMB     64
#define G2      16
#define OUT_SZ  5
#define AK      256      // combined inner dim: [ie(64) | te(64) | h(128)]
#define GATES   512

// -------- device scratch (static; no allocation) --------
__device__ float g_Wr[AK * GATES];    // rearranged combined weights: col' = unit*4 + gate
__device__ float g_br[GATES];         // b_ih + b_hh, rearranged
__device__ int   g_winner[N_NODES];   // last-wins stamp per node
__device__ float g_hs[K_ACT * RNN];   // per-frame h_new scratch
__device__ float g_cs[K_ACT * RNN];   // per-frame c_new scratch

// ---------------------------------------------------------------------------
// One-time weight rearrangement: Wr[r][unit*4+gate] = {W_ih|W_hh}[r][gate*128+unit]
// so each thread's 4 adjacent output columns are the (i,f,g,o) gates of one unit.
// ---------------------------------------------------------------------------
__global__ void init_weights_kernel(const float* __restrict__ W_ih, const float* __restrict__ b_ih,
                                    const float* __restrict__ W_hh, const float* __restrict__ b_hh)
{
    int r  = blockIdx.x;     // 0..255
    int cp = threadIdx.x;    // 0..511
    int unit = cp >> 2, gate = cp & 3;
    int col = gate * RNN + unit;
    float v = (r < RNN) ? W_ih[r * GATES + col] : W_hh[(r - RNN) * GATES + col];
    g_Wr[r * GATES + cp] = v;
    if (r == 0) g_br[cp] = b_ih[col] + b_hh[col];
}

// ---------------------------------------------------------------------------
// Per-launch init: zero outputs, copy h0/c0 into the state tail of d_out,
// reset winner stamps (required for graph replay determinism).
// ---------------------------------------------------------------------------
__global__ void init_state_kernel(float* __restrict__ out,
                                  const float* __restrict__ h0, const float* __restrict__ c0)
{
    const int OUT_TOTAL = T_STEPS * N_NODES * OUT_SZ;   // 5,000,000
    const int HOFF = OUT_TOTAL;
    const int COFF = HOFF + N_NODES * RNN;              // 11,400,000
    const int WOFF = COFF + N_NODES * RNN;              // 17,800,000
    const int TOTAL = WOFF + N_NODES;
    for (int i = blockIdx.x * blockDim.x + threadIdx.x; i < TOTAL; i += gridDim.x * blockDim.x) {
        if (i < OUT_TOTAL)      out[i] = 0.f;
        else if (i < COFF)      out[i] = h0[i - HOFF];
        else if (i < WOFF)      out[i] = c0[i - COFF];
        else                    g_winner[i - WOFF] = -1;
    }
}

// ---------------------------------------------------------------------------
// Per-frame winner stamping: last occurrence (max k) wins, matching JAX
// .at[idx].set in-order update semantics.
// ---------------------------------------------------------------------------
__global__ void stamp_kernel(const int* __restrict__ active_idx, int t)
{
    int k = blockIdx.x * blockDim.x + threadIdx.x;
    if (k < K_ACT) atomicMax(&g_winner[active_idx[t * K_ACT + k]], t * K_ACT + k);
}

// ---------------------------------------------------------------------------
// Main per-frame kernel: build A-tile (embeddings + h gather) in smem,
// tiled GEMM [64 rows x 128 rearranged cols], LSTM pointwise epilogue,
// results to scratch (race-free vs. the state buffers).
// grid = (ceil(K/64), 4), block = 256, dyn smem ~82KB
// ---------------------------------------------------------------------------
__global__ __launch_bounds__(256) void frame_kernel(
    const float* __restrict__ input_data, const float* __restrict__ grids,
    const int*   __restrict__ active_idx,
    const float* __restrict__ W_in, const float* __restrict__ b_in,
    const float* __restrict__ W_obs, const float* __restrict__ b_obs,
    const float* __restrict__ h_all, const float* __restrict__ c_all,
    int t)
{
    extern __shared__ float smem[];
    float* A_s  = smem;                       // [AK][64], layout A_s[kk*64 + row]
    float* B_s  = smem + AK * 64;             // [32][128]
    int*   nid_s = (int*)(B_s + 32 * 128);    // [64]

    const int tid   = threadIdx.x;
    const int r0    = blockIdx.x * 64;
    const int cbase = blockIdx.y * 128;       // rearranged col offset (units cbase/4 .. +31)

    // ---- Phase 1: build A tile (4 threads per row, 64 A-elements each) ----
    {
        int row = tid >> 2, part = tid & 3;
        int k = r0 + row;
        if (k < K_ACT) {
            int n = active_idx[t * K_ACT + k];
            if (part == 0) {
                nid_s[row] = n;
                float x0 = input_data[(t * N_NODES + n) * 2 + 0];
                float x1 = input_data[(t * N_NODES + n) * 2 + 1];
                #pragma unroll
                for (int j = 0; j < EMB; j++) {
                    float v = fmaf(x0, W_in[j], fmaf(x1, W_in[EMB + j], b_in[j]));
                    A_s[j * 64 + row] = fmaxf(v, 0.f);
                }
            } else if (part == 1) {
                float obs[G2];
                const float* gp = grids + (t * K_ACT + k) * G2;
                #pragma unroll
                for (int g = 0; g < G2; g++) obs[g] = gp[g];
                #pragma unroll 4
                for (int j = 0; j < EMB; j++) {
                    float acc = b_obs[j];
                    #pragma unroll
                    for (int g = 0; g < G2; g++) acc = fmaf(obs[g], W_obs[g * EMB + j], acc);
                    A_s[(EMB + j) * 64 + row] = fmaxf(acc, 0.f);
                }
            } else {
                int h0i = (part - 2) * 64;    // 0 or 64
                const float* hp = h_all + (size_t)n * RNN + h0i;
                #pragma unroll
                for (int j = 0; j < 64; j += 4) {
                    float4 h4 = *(const float4*)(hp + j);
                    A_s[(2 * EMB + h0i + j + 0) * 64 + row] = h4.x;
                    A_s[(2 * EMB + h0i + j + 1) * 64 + row] = h4.y;
                    A_s[(2 * EMB + h0i + j + 2) * 64 + row] = h4.z;
                    A_s[(2 * EMB + h0i + j + 3) * 64 + row] = h4.w;
                }
            }
        } else {
            for (int j = 0; j < 64; j++) A_s[(part * 64 + j) * 64 + row] = 0.f;
        }
    }
    __syncthreads();

    // ---- Phase 2: GEMM. Thread = (ty row-group of 8, tx unit of 4 gate-cols) ----
    const int tx = tid & 31, ty = tid >> 5;
    float acc[8][4];
    #pragma unroll
    for (int r = 0; r < 8; r++) { acc[r][0] = 0.f; acc[r][1] = 0.f; acc[r][2] = 0.f; acc[r][3] = 0.f; }

    for (int chunk = 0; chunk < 8; chunk++) {
        int kkb = chunk * 32;
        // stage B chunk [32][128] (coalesced float4 loads)
        #pragma unroll
        for (int i = 0; i < 4; i++) {
            int lin4 = tid + i * 256;      // 1024 float4s total
            int rr = lin4 >> 5;            // 0..31
            int c4 = lin4 & 31;
            *(float4*)&B_s[rr * 128 + c4 * 4] =
                *(const float4*)&g_Wr[(kkb + rr) * GATES + cbase + c4 * 4];
        }
        __syncthreads();
        #pragma unroll
        for (int kk = 0; kk < 32; kk++) {
            float4 b = *(float4*)&B_s[kk * 128 + tx * 4];
            const float* ap = &A_s[(kkb + kk) * 64 + ty * 8];
            float4 a0 = *(const float4*)ap;
            float4 a1 = *(const float4*)(ap + 4);
            float av[8] = {a0.x, a0.y, a0.z, a0.w, a1.x, a1.y, a1.z, a1.w};
            #pragma unroll
            for (int r = 0; r < 8; r++) {
                acc[r][0] = fmaf(av[r], b.x, acc[r][0]);
                acc[r][1] = fmaf(av[r], b.y, acc[r][1]);
                acc[r][2] = fmaf(av[r], b.z, acc[r][2]);
                acc[r][3] = fmaf(av[r], b.w, acc[r][3]);
            }
        }
        __syncthreads();
    }

    // ---- Phase 3: LSTM pointwise epilogue (thread-local: 4 cols = i,f,g,o of one unit) ----
    const int u = blockIdx.y * 32 + tx;         // unit index 0..127
    float4 brv = *(float4*)&g_br[u * 4];
    #pragma unroll
    for (int r = 0; r < 8; r++) {
        int row = ty * 8 + r;
        int k = r0 + row;
        if (k < K_ACT) {
            int n = nid_s[row];
            float gi = 1.f / (1.f + __expf(-(acc[r][0] + brv.x)));
            float gf = 1.f / (1.f + __expf(-(acc[r][1] + brv.y)));
            float gg = tanhf(acc[r][2] + brv.z);
            float go = 1.f / (1.f + __expf(-(acc[r][3] + brv.w)));
            float co = c_all[(size_t)n * RNN + u];
            float cn = fmaf(gf, co, gi * gg);
            float hn = go * tanhf(cn);
            g_hs[k * RNN + u] = hn;
            g_cs[k * RNN + u] = cn;
        }
    }
}

// ---------------------------------------------------------------------------
// Per-frame scatter: winners write h/c back to state and compute out = h@W_out+b.
// One warp per active slot.
// ---------------------------------------------------------------------------
__global__ __launch_bounds__(256) void scatter_kernel(
    const int*   __restrict__ active_idx,
    const float* __restrict__ W_out, const float* __restrict__ b_out,
    float* __restrict__ outputs, float* __restrict__ h_all, float* __restrict__ c_all,
    int t)
{
    int lane = threadIdx.x & 31;
    int k = blockIdx.x * 8 + (threadIdx.x >> 5);
    if (k >= K_ACT) return;
    int n = active_idx[t * K_ACT + k];
    if (g_winner[n] != t * K_ACT + k) return;   // last-occurrence wins

    float4 h4 = *(float4*)&g_hs[k * RNN + lane * 4];
    float4 c4 = *(float4*)&g_cs[k * RNN + lane * 4];
    *(float4*)&h_all[(size_t)n * RNN + lane * 4] = h4;
    *(float4*)&c_all[(size_t)n * RNN + lane * 4] = c4;

    float p[OUT_SZ];
    int i0 = lane * 4;
    #pragma unroll
    for (int j = 0; j < OUT_SZ; j++) {
        p[j] = h4.x * W_out[(i0 + 0) * OUT_SZ + j]
             + h4.y * W_out[(i0 + 1) * OUT_SZ + j]
             + h4.z * W_out[(i0 + 2) * OUT_SZ + j]
             + h4.w * W_out[(i0 + 3) * OUT_SZ + j];
    }
    #pragma unroll
    for (int off = 16; off > 0; off >>= 1) {
        #pragma unroll
        for (int j = 0; j < OUT_SZ; j++)
            p[j] += __shfl_down_sync(0xffffffffu, p[j], off);
    }
    if (lane == 0) {
        #pragma unroll
        for (int j = 0; j < OUT_SZ; j++)
            outputs[((size_t)t * N_NODES + n) * OUT_SZ + j] = p[j] + b_out[j];
    }
}

// ---------------------------------------------------------------------------
extern "C" void kernel_launch(void* const* d_in, const int* in_sizes, int n_in,
                              void* d_out, int out_size)
{
    const float* input_data = (const float*)d_in[0];
    const float* grids      = (const float*)d_in[1];
    const float* h0         = (const float*)d_in[2];
    const float* c0         = (const float*)d_in[3];
    const int*   active_idx = (const int*)  d_in[4];
    const float* W_in       = (const float*)d_in[5];
    const float* b_in       = (const float*)d_in[6];
    const float* W_obs      = (const float*)d_in[7];
    const float* b_obs      = (const float*)d_in[8];
    const float* W_ih       = (const float*)d_in[9];
    const float* b_ih       = (const float*)d_in[10];
    const float* W_hh       = (const float*)d_in[11];
    const float* b_hh       = (const float*)d_in[12];
    const float* W_out      = (const float*)d_in[13];
    const float* b_out      = (const float*)d_in[14];

    float* out     = (float*)d_out;
    float* outputs = out;                                        // [T,N,5]
    float* h_all   = out + (size_t)T_STEPS * N_NODES * OUT_SZ;   // [N,128] live state == h_fin
    float* c_all   = h_all + (size_t)N_NODES * RNN;              // [N,128] live state == c_fin

    size_t smem_bytes = (size_t)(AK * 64 + 32 * 128) * sizeof(float) + 64 * sizeof(int);
    cudaFuncSetAttribute(frame_kernel, cudaFuncAttributeMaxDynamicSharedMemorySize, (int)smem_bytes);

    init_weights_kernel<<<AK, GATES>>>(W_ih, b_ih, W_hh, b_hh);
    init_state_kernel<<<1024, 256>>>(out, h0, c0);

    dim3 ggrid((K_ACT + 63) / 64, 4);
    for (int t = 0; t < T_STEPS; t++) {
        stamp_kernel<<<(K_ACT + 255) / 256, 256>>>(active_idx, t);
        frame_kernel<<<ggrid, 256, smem_bytes>>>(input_data, grids, active_idx,
                                                 W_in, b_in, W_obs, b_obs,
                                                 h_all, c_all, t);
        scatter_kernel<<<(K_ACT + 7) / 8, 256>>>(active_idx, W_out, b_out,
                                                 outputs, h_all, c_all, t);
    }
}

// round 4
// speedup vs baseline: 2.0279x; 2.0279x over previous
#include <cuda_runtime.h>
#include <cstdint>

#define T_STEPS 20
#define N_NODES 50000
#define K_ACT   10000
#define RNN     128
#define OUT_SZ  5
#define M_TILES 79
#define MG_CNT  (M_TILES * 8)     // 632 groups of 16 rows

// -------- device scratch (static; no allocation) --------
// A in m16k8 tf32 fragment layout: [mg][k8][lane][4]
__device__ float4 g_Afrag[(size_t)MG_CNT * 32 * 32];
// B in k8n8 tf32 fragment layout: [nf][k8][lane][2]  (nf = col'/8, col' = unit*4+gate)
__device__ float2 g_Bfrag[64 * 32 * 32];
__device__ float4 g_br[RNN];                   // per-unit (bi,bf,bg,bo) = b_ih+b_hh rearranged
__device__ float  g_cg[(size_t)K_ACT * RNN];   // dense c gather per frame
__device__ float  g_hs[(size_t)K_ACT * RNN];   // h_new scratch
__device__ float  g_cs[(size_t)K_ACT * RNN];   // c_new scratch
__device__ int    g_winner[N_NODES];           // last-wins stamps

// ======================= helpers =======================
__device__ __forceinline__ float tf32r(float x) {   // round-to-nearest tf32
    uint32_t y;
    asm("cvt.rna.tf32.f32 %0, %1;" : "=r"(y) : "f"(x));
    return __uint_as_float(y);
}
__device__ __forceinline__ float sigf(float x)   { return __fdividef(1.f, 1.f + __expf(-x)); }
__device__ __forceinline__ float tanhfa(float x) { return __fdividef(2.f, 1.f + __expf(-2.f * x)) - 1.f; }

// Scatter one A value (row m, col j) into the fragment layout.
__device__ __forceinline__ void writeA(int m, int j, float v) {
    int mg = m >> 4, r = m & 15;
    int k8 = j >> 3;
    int lane = (r & 7) * 4 + (j & 3);
    int reg  = ((j >> 2) & 1) * 2 + (r >> 3);
    ((float*)g_Afrag)[((((size_t)mg * 32 + k8) * 32) + lane) * 4 + reg] = v;
}

#define MMA_TF32(cc, aa, bb) \
    asm volatile("mma.sync.aligned.m16n8k8.row.col.f32.tf32.tf32.f32 " \
        "{%0,%1,%2,%3},{%4,%5,%6,%7},{%8,%9},{%0,%1,%2,%3};" \
        : "+f"((cc)[0]), "+f"((cc)[1]), "+f"((cc)[2]), "+f"((cc)[3]) \
        : "r"(__float_as_uint((aa).x)), "r"(__float_as_uint((aa).y)), \
          "r"(__float_as_uint((aa).z)), "r"(__float_as_uint((aa).w)), \
          "r"(__float_as_uint((bb).x)), "r"(__float_as_uint((bb).y)))

// ======================= init kernels =======================
__global__ void init_weights_kernel(const float* __restrict__ W_ih, const float* __restrict__ b_ih,
                                    const float* __restrict__ W_hh, const float* __restrict__ b_hh)
{
    int cp = blockIdx.x;     // rearranged column col' = unit*4+gate, 0..511
    int r  = threadIdx.x;    // inner k, 0..255
    int unit = cp >> 2, gate = cp & 3;
    int col = gate * RNN + unit;
    float v = (r < RNN) ? W_ih[r * 512 + col] : W_hh[(r - RNN) * 512 + col];
    int nf = cp >> 3, lane = (cp & 7) * 4 + (r & 3), reg = (r >> 2) & 1, k8 = r >> 3;
    ((float*)g_Bfrag)[(((size_t)nf * 32 + k8) * 32 + lane) * 2 + reg] = tf32r(v);
    if (r == 0) ((float*)g_br)[cp] = b_ih[col] + b_hh[col];
}

__global__ void init_state_kernel(float* __restrict__ out,
                                  const float* __restrict__ h0, const float* __restrict__ c0)
{
    const int OUT_TOTAL = T_STEPS * N_NODES * OUT_SZ;
    const int HOFF = OUT_TOTAL;
    const int COFF = HOFF + N_NODES * RNN;
    const int WOFF = COFF + N_NODES * RNN;
    const int TOTAL = WOFF + N_NODES;
    for (int i = blockIdx.x * blockDim.x + threadIdx.x; i < TOTAL; i += gridDim.x * blockDim.x) {
        if (i < OUT_TOTAL)      out[i] = 0.f;
        else if (i < COFF)      out[i] = h0[i - HOFF];
        else if (i < WOFF)      out[i] = c0[i - COFF];
        else                    g_winner[i - WOFF] = -1;
    }
}

// ======================= per-frame: embed + gather + stamp =======================
__global__ __launch_bounds__(256) void embed_kernel(
    const float* __restrict__ input_data, const float* __restrict__ grids,
    const int* __restrict__ active_idx,
    const float* __restrict__ W_in, const float* __restrict__ b_in,
    const float* __restrict__ W_obs, const float* __restrict__ b_obs,
    const float* __restrict__ h_all, const float* __restrict__ c_all, int t)
{
    int wid = threadIdx.x >> 5, lane = threadIdx.x & 31;
    int k = blockIdx.x * 8 + wid;
    if (k >= K_ACT) return;
    int n = active_idx[t * K_ACT + k];
    if (lane == 0) atomicMax(&g_winner[n], t * K_ACT + k);

    // h gather -> A cols 128..255 (tf32); c gather -> dense scratch
    float4 h4 = *(const float4*)&h_all[(size_t)n * RNN + lane * 4];
    int jh = 128 + lane * 4;
    writeA(k, jh + 0, tf32r(h4.x));
    writeA(k, jh + 1, tf32r(h4.y));
    writeA(k, jh + 2, tf32r(h4.z));
    writeA(k, jh + 3, tf32r(h4.w));
    float4 c4 = *(const float4*)&c_all[(size_t)n * RNN + lane * 4];
    *(float4*)&g_cg[(size_t)k * RNN + lane * 4] = c4;

    // input embedding -> A cols 0..63
    float x0 = input_data[((size_t)t * N_NODES + n) * 2 + 0];
    float x1 = input_data[((size_t)t * N_NODES + n) * 2 + 1];
    #pragma unroll
    for (int jj = 0; jj < 2; jj++) {
        int j = lane + jj * 32;
        float v = fmaf(x0, W_in[j], fmaf(x1, W_in[64 + j], b_in[j]));
        writeA(k, j, tf32r(fmaxf(v, 0.f)));
    }
    // grid (social tensor) embedding -> A cols 64..127
    const float* gp = grids + ((size_t)t * K_ACT + k) * 16;
    float obs[16];
    #pragma unroll
    for (int g = 0; g < 16; g++) obs[g] = gp[g];
    #pragma unroll
    for (int jj = 0; jj < 2; jj++) {
        int j = lane + jj * 32;
        float acc = b_obs[j];
        #pragma unroll
        for (int g = 0; g < 16; g++) acc = fmaf(obs[g], W_obs[g * 64 + j], acc);
        writeA(k, 64 + j, tf32r(fmaxf(acc, 0.f)));
    }
}

// ======================= per-frame: mma.sync tf32 GEMM + LSTM epilogue =======================
// grid (79, 4), 256 threads. Block tile 128m x 128n; warp tile 32m x 64n.
__global__ __launch_bounds__(256) void gemm_kernel()
{
    const int tid = threadIdx.x, wid = tid >> 5, lane = tid & 31;
    const int wm = wid & 3, wn = wid >> 2;
    const int bx = blockIdx.x, ny = blockIdx.y;
    const int g = lane >> 2, tg = lane & 3;

    float c[2][8][4];
    #pragma unroll
    for (int f = 0; f < 2; f++)
        #pragma unroll
        for (int j = 0; j < 8; j++)
            { c[f][j][0] = 0.f; c[f][j][1] = 0.f; c[f][j][2] = 0.f; c[f][j][3] = 0.f; }

    const float4* A0 = g_Afrag + ((size_t)(bx * 8 + wm * 2) * 32) * 32 + lane;
    const float4* A1 = A0 + 32 * 32;
    const float2* Bq = g_Bfrag + ((size_t)(ny * 16 + wn * 8) * 32) * 32 + lane;

    #pragma unroll 4
    for (int k8 = 0; k8 < 32; k8++) {
        float4 a0 = A0[k8 * 32];
        float4 a1 = A1[k8 * 32];
        float2 bf[8];
        #pragma unroll
        for (int j = 0; j < 8; j++) bf[j] = Bq[(size_t)j * 32 * 32 + k8 * 32];
        #pragma unroll
        for (int j = 0; j < 8; j++) {
            MMA_TF32(c[0][j], a0, bf[j]);
            MMA_TF32(c[1][j], a1, bf[j]);
        }
    }

    // ---- LSTM epilogue ----
    // C frag: thread (g,tg) holds cols {2tg, 2tg+1} (= gates (i,f) if tg even, (g,o) if odd,
    // of unit u = nf*2 + tg/2) for rows g (c0,c1) and g+8 (c2,c3).
    #pragma unroll
    for (int f = 0; f < 2; f++) {
        #pragma unroll
        for (int j = 0; j < 8; j++) {
            float x0 = __shfl_xor_sync(0xffffffffu, c[f][j][0], 1);
            float x1 = __shfl_xor_sync(0xffffffffu, c[f][j][1], 1);
            float x2 = __shfl_xor_sync(0xffffffffu, c[f][j][2], 1);
            float x3 = __shfl_xor_sync(0xffffffffu, c[f][j][3], 1);
            // even lane -> row g; odd lane -> row g+8
            int odd = lane & 1;
            float gi = odd ? x2 : c[f][j][0];
            float gf = odd ? x3 : c[f][j][1];
            float gg = odd ? c[f][j][2] : x0;
            float go = odd ? c[f][j][3] : x1;
            int row = bx * 128 + wm * 32 + f * 16 + g + odd * 8;
            if (row < K_ACT) {
                int u = (ny * 16 + wn * 8 + j) * 2 + (tg >> 1);
                float4 br = g_br[u];
                float co = g_cg[(size_t)row * RNN + u];
                float ii = sigf(gi + br.x);
                float ff = sigf(gf + br.y);
                float G  = tanhfa(gg + br.z);
                float oo = sigf(go + br.w);
                float cn = fmaf(ff, co, ii * G);
                float hn = oo * tanhfa(cn);
                g_hs[(size_t)row * RNN + u] = hn;
                g_cs[(size_t)row * RNN + u] = cn;
            }
        }
    }
}

// ======================= per-frame: winner scatter + output projection =======================
__global__ __launch_bounds__(256) void scatter_kernel(
    const int* __restrict__ active_idx,
    const float* __restrict__ W_out, const float* __restrict__ b_out,
    float* __restrict__ outputs, float* __restrict__ h_all, float* __restrict__ c_all, int t)
{
    int lane = threadIdx.x & 31;
    int k = blockIdx.x * 8 + (threadIdx.x >> 5);
    if (k >= K_ACT) return;
    int n = active_idx[t * K_ACT + k];
    if (g_winner[n] != t * K_ACT + k) return;   // last-occurrence wins

    float4 h4 = *(float4*)&g_hs[(size_t)k * RNN + lane * 4];
    float4 c4 = *(float4*)&g_cs[(size_t)k * RNN + lane * 4];
    *(float4*)&h_all[(size_t)n * RNN + lane * 4] = h4;
    *(float4*)&c_all[(size_t)n * RNN + lane * 4] = c4;

    float p[OUT_SZ];
    int i0 = lane * 4;
    #pragma unroll
    for (int j = 0; j < OUT_SZ; j++) {
        p[j] = h4.x * W_out[(i0 + 0) * OUT_SZ + j]
             + h4.y * W_out[(i0 + 1) * OUT_SZ + j]
             + h4.z * W_out[(i0 + 2) * OUT_SZ + j]
             + h4.w * W_out[(i0 + 3) * OUT_SZ + j];
    }
    #pragma unroll
    for (int off = 16; off > 0; off >>= 1) {
        #pragma unroll
        for (int j = 0; j < OUT_SZ; j++)
            p[j] += __shfl_down_sync(0xffffffffu, p[j], off);
    }
    if (lane == 0) {
        #pragma unroll
        for (int j = 0; j < OUT_SZ; j++)
            outputs[((size_t)t * N_NODES + n) * OUT_SZ + j] = p[j] + b_out[j];
    }
}

// ======================= launcher =======================
extern "C" void kernel_launch(void* const* d_in, const int* in_sizes, int n_in,
                              void* d_out, int out_size)
{
    const float* input_data = (const float*)d_in[0];
    const float* grids      = (const float*)d_in[1];
    const float* h0         = (const float*)d_in[2];
    const float* c0         = (const float*)d_in[3];
    const int*   active_idx = (const int*)  d_in[4];
    const float* W_in       = (const float*)d_in[5];
    const float* b_in       = (const float*)d_in[6];
    const float* W_obs      = (const float*)d_in[7];
    const float* b_obs      = (const float*)d_in[8];
    const float* W_ih       = (const float*)d_in[9];
    const float* b_ih       = (const float*)d_in[10];
    const float* W_hh       = (const float*)d_in[11];
    const float* b_hh       = (const float*)d_in[12];
    const float* W_out      = (const float*)d_in[13];
    const float* b_out      = (const float*)d_in[14];

    float* out     = (float*)d_out;
    float* outputs = out;
    float* h_all   = out + (size_t)T_STEPS * N_NODES * OUT_SZ;
    float* c_all   = h_all + (size_t)N_NODES * RNN;

    init_weights_kernel<<<512, 256>>>(W_ih, b_ih, W_hh, b_hh);
    init_state_kernel<<<1024, 256>>>(out, h0, c0);

    for (int t = 0; t < T_STEPS; t++) {
        embed_kernel<<<(K_ACT + 7) / 8, 256>>>(input_data, grids, active_idx,
                                               W_in, b_in, W_obs, b_obs, h_all, c_all, t);
        gemm_kernel<<<dim3(M_TILES, 4), 256>>>();
        scatter_kernel<<<(K_ACT + 7) / 8, 256>>>(active_idx, W_out, b_out,
                                                 outputs, h_all, c_all, t);
    }
}

// round 7
// speedup vs baseline: 2.8193x; 1.3902x over previous
#include <cuda_runtime.h>
#include <cuda_fp16.h>
#include <cstdint>
#include <cstring>

#define T_STEPS 20
#define N_NODES 50000
#define K_ACT   10000
#define RNN     128
#define OUT_SZ  5
#define M_TILES 79
#define MG_CNT  (M_TILES * 8)     // 632 groups of 16 rows
#define K16     16                // 256 / 16

// -------- device scratch (static; no allocation) --------
// A in m16n8k16 fp16 fragment layout: [mg][k16][lane] -> uint4 (regs a0..a3)
__device__ uint4 g_Afrag[(size_t)MG_CNT * K16 * 32];
// B in k16n8 fp16 fragment layout: [nf][k16][lane] -> uint2 (regs b0,b1)
__device__ uint2 g_Bfrag[64 * K16 * 32];
__device__ float4 g_br[RNN];                   // per-unit (bi,bf,bg,bo)
__device__ float  g_cg[(size_t)K_ACT * RNN];   // dense c gather per frame
__device__ float  g_hs[(size_t)K_ACT * RNN];   // h_new scratch
__device__ float  g_cs[(size_t)K_ACT * RNN];   // c_new scratch
__device__ int    g_winner[N_NODES];           // last-wins stamps

// ======================= helpers =======================
__device__ __forceinline__ float sigf(float x)   { return __fdividef(1.f, 1.f + __expf(-x)); }
__device__ __forceinline__ float tanhfa(float x) { return __fdividef(2.f, 1.f + __expf(-2.f * x)) - 1.f; }

__device__ __forceinline__ uint32_t h2u(__half2 v) {
    uint32_t u;
    memcpy(&u, &v, 4);
    return u;
}

// Write an even-aligned (col j, j+1) half2 pair of A in fragment layout.
__device__ __forceinline__ void writeA2(int m, int j, __half2 v) {
    int mg = m >> 4, r = m & 15;
    int k16 = j >> 4, kk = j & 15;                 // kk even
    int lane = (r & 7) * 4 + ((kk & 7) >> 1);
    int reg  = ((kk >> 3) << 1) | (r >> 3);
    ((uint32_t*)g_Afrag)[((((size_t)mg * K16 + k16) * 32) + lane) * 4 + reg] = h2u(v);
}

#define MMA_F16(cc, aa, bb) \
    asm volatile("mma.sync.aligned.m16n8k16.row.col.f32.f16.f16.f32 " \
        "{%0,%1,%2,%3},{%4,%5,%6,%7},{%8,%9},{%0,%1,%2,%3};" \
        : "+f"((cc)[0]), "+f"((cc)[1]), "+f"((cc)[2]), "+f"((cc)[3]) \
        : "r"((aa).x), "r"((aa).y), "r"((aa).z), "r"((aa).w), \
          "r"((bb).x), "r"((bb).y))

// ======================= init kernels =======================
__global__ void init_weights_kernel(const float* __restrict__ W_ih, const float* __restrict__ b_ih,
                                    const float* __restrict__ W_hh, const float* __restrict__ b_hh)
{
    int cp = blockIdx.x;     // rearranged column col' = unit*4+gate, 0..511
    int r  = threadIdx.x;    // inner k, 0..255
    int unit = cp >> 2, gate = cp & 3;
    int col = gate * RNN + unit;
    float v = (r < RNN) ? W_ih[r * 512 + col] : W_hh[(r - RNN) * 512 + col];
    // f16 B fragment: lane=(n&7)*4 + ((k&7)>>1), reg=(k>>3)&1, halfpos=k&1, k16=k>>4
    int nf = cp >> 3;
    int lane = (cp & 7) * 4 + ((r & 7) >> 1);
    int reg = (r >> 3) & 1, halfpos = r & 1, k16 = r >> 4;
    ((__half*)g_Bfrag)[((((size_t)nf * K16 + k16) * 32 + lane) * 2 + reg) * 2 + halfpos] = __float2half_rn(v);
    if (r == 0) ((float*)g_br)[cp] = b_ih[col] + b_hh[col];
}

__global__ void init_state_kernel(float* __restrict__ out,
                                  const float* __restrict__ h0, const float* __restrict__ c0)
{
    const int OUT_TOTAL = T_STEPS * N_NODES * OUT_SZ;
    const int HOFF = OUT_TOTAL;
    const int COFF = HOFF + N_NODES * RNN;
    const int WOFF = COFF + N_NODES * RNN;
    const int TOTAL = WOFF + N_NODES;
    for (int i = blockIdx.x * blockDim.x + threadIdx.x; i < TOTAL; i += gridDim.x * blockDim.x) {
        if (i < OUT_TOTAL)      out[i] = 0.f;
        else if (i < COFF)      out[i] = h0[i - HOFF];
        else if (i < WOFF)      out[i] = c0[i - COFF];
        else                    g_winner[i - WOFF] = -1;
    }
}

// ======================= per-frame: embed + gather + stamp =======================
__global__ __launch_bounds__(256) void embed_kernel(
    const float* __restrict__ input_data, const float* __restrict__ grids,
    const int* __restrict__ active_idx,
    const float* __restrict__ W_in, const float* __restrict__ b_in,
    const float* __restrict__ W_obs, const float* __restrict__ b_obs,
    const float* __restrict__ h_all, const float* __restrict__ c_all, int t)
{
    int wid = threadIdx.x >> 5, lane = threadIdx.x & 31;
    int k = blockIdx.x * 8 + wid;
    if (k >= K_ACT) return;
    int n = active_idx[t * K_ACT + k];
    if (lane == 0) atomicMax(&g_winner[n], t * K_ACT + k);

    // h gather -> A cols 128..255 (fp16); c gather -> dense scratch
    float4 h4 = *(const float4*)&h_all[(size_t)n * RNN + lane * 4];
    int jh = 128 + lane * 4;
    writeA2(k, jh + 0, __floats2half2_rn(h4.x, h4.y));
    writeA2(k, jh + 2, __floats2half2_rn(h4.z, h4.w));
    float4 c4 = *(const float4*)&c_all[(size_t)n * RNN + lane * 4];
    *(float4*)&g_cg[(size_t)k * RNN + lane * 4] = c4;

    // input embedding -> A cols 0..63 (this thread: cols 2*lane, 2*lane+1)
    float x0 = input_data[((size_t)t * N_NODES + n) * 2 + 0];
    float x1 = input_data[((size_t)t * N_NODES + n) * 2 + 1];
    {
        int j = 2 * lane;
        float v0 = fmaf(x0, W_in[j],     fmaf(x1, W_in[64 + j],     b_in[j]));
        float v1 = fmaf(x0, W_in[j + 1], fmaf(x1, W_in[64 + j + 1], b_in[j + 1]));
        writeA2(k, j, __floats2half2_rn(fmaxf(v0, 0.f), fmaxf(v1, 0.f)));
    }
    // grid embedding -> A cols 64..127 (this thread: cols 64+2*lane, +1)
    const float* gp = grids + ((size_t)t * K_ACT + k) * 16;
    float obs[16];
    #pragma unroll
    for (int g = 0; g < 16; g++) obs[g] = gp[g];
    {
        int j = 2 * lane;
        float a0 = b_obs[j], a1 = b_obs[j + 1];
        #pragma unroll
        for (int g = 0; g < 16; g++) {
            a0 = fmaf(obs[g], W_obs[g * 64 + j],     a0);
            a1 = fmaf(obs[g], W_obs[g * 64 + j + 1], a1);
        }
        writeA2(k, 64 + j, __floats2half2_rn(fmaxf(a0, 0.f), fmaxf(a1, 0.f)));
    }
}

// ======================= per-frame: mma.sync fp16 GEMM + LSTM epilogue =======================
// grid (79, 4), 256 threads (2 CTAs/SM). Block tile 128m x 128n; warp tile 32m x 64n.
// K = 256 in 16 k16-steps, explicit next-step register prefetch.
__global__ __launch_bounds__(256, 2) void gemm_kernel()
{
    const int tid = threadIdx.x, wid = tid >> 5, lane = tid & 31;
    const int wm = wid & 3, wn = wid >> 2;
    const int bx = blockIdx.x, ny = blockIdx.y;
    const int g = lane >> 2, tg = lane & 3;

    float c[2][8][4];
    #pragma unroll
    for (int f = 0; f < 2; f++)
        #pragma unroll
        for (int j = 0; j < 8; j++)
            { c[f][j][0] = 0.f; c[f][j][1] = 0.f; c[f][j][2] = 0.f; c[f][j][3] = 0.f; }

    const uint4* A0 = g_Afrag + ((size_t)(bx * 8 + wm * 2) * K16) * 32 + lane;
    const uint4* A1 = A0 + K16 * 32;
    const uint2* Bq = g_Bfrag + ((size_t)(ny * 16 + wn * 8) * K16) * 32 + lane;

    uint4 a0 = A0[0], a1 = A1[0];
    uint2 bf[8];
    #pragma unroll
    for (int j = 0; j < 8; j++) bf[j] = Bq[(size_t)j * K16 * 32];

    #pragma unroll
    for (int k16 = 0; k16 < K16; k16++) {
        uint4 na0, na1;
        uint2 nbf[8];
        if (k16 < K16 - 1) {
            na0 = A0[(k16 + 1) * 32];
            na1 = A1[(k16 + 1) * 32];
            #pragma unroll
            for (int j = 0; j < 8; j++) nbf[j] = Bq[(size_t)j * K16 * 32 + (k16 + 1) * 32];
        }
        #pragma unroll
        for (int j = 0; j < 8; j++) {
            MMA_F16(c[0][j], a0, bf[j]);
            MMA_F16(c[1][j], a1, bf[j]);
        }
        if (k16 < K16 - 1) {
            a0 = na0; a1 = na1;
            #pragma unroll
            for (int j = 0; j < 8; j++) bf[j] = nbf[j];
        }
    }

    // ---- LSTM epilogue (C layout identical to tf32 path) ----
    #pragma unroll
    for (int f = 0; f < 2; f++) {
        #pragma unroll
        for (int j = 0; j < 8; j++) {
            float x0 = __shfl_xor_sync(0xffffffffu, c[f][j][0], 1);
            float x1 = __shfl_xor_sync(0xffffffffu, c[f][j][1], 1);
            float x2 = __shfl_xor_sync(0xffffffffu, c[f][j][2], 1);
            float x3 = __shfl_xor_sync(0xffffffffu, c[f][j][3], 1);
            int odd = lane & 1;
            float gi = odd ? x2 : c[f][j][0];
            float gf = odd ? x3 : c[f][j][1];
            float gg = odd ? c[f][j][2] : x0;
            float go = odd ? c[f][j][3] : x1;
            int row = bx * 128 + wm * 32 + f * 16 + g + odd * 8;
            if (row < K_ACT) {
                int u = (ny * 16 + wn * 8 + j) * 2 + (tg >> 1);
                float4 br = g_br[u];
                float co = g_cg[(size_t)row * RNN + u];
                float ii = sigf(gi + br.x);
                float ff = sigf(gf + br.y);
                float G  = tanhfa(gg + br.z);
                float oo = sigf(go + br.w);
                float cn = fmaf(ff, co, ii * G);
                float hn = oo * tanhfa(cn);
                g_hs[(size_t)row * RNN + u] = hn;
                g_cs[(size_t)row * RNN + u] = cn;
            }
        }
    }
}

// ======================= per-frame: winner scatter + output projection =======================
__global__ __launch_bounds__(256) void scatter_kernel(
    const int* __restrict__ active_idx,
    const float* __restrict__ W_out, const float* __restrict__ b_out,
    float* __restrict__ outputs, float* __restrict__ h_all, float* __restrict__ c_all, int t)
{
    int lane = threadIdx.x & 31;
    int k = blockIdx.x * 8 + (threadIdx.x >> 5);
    if (k >= K_ACT) return;
    int n = active_idx[t * K_ACT + k];
    if (g_winner[n] != t * K_ACT + k) return;   // last-occurrence wins

    float4 h4 = *(float4*)&g_hs[(size_t)k * RNN + lane * 4];
    float4 c4 = *(float4*)&g_cs[(size_t)k * RNN + lane * 4];
    *(float4*)&h_all[(size_t)n * RNN + lane * 4] = h4;
    *(float4*)&c_all[(size_t)n * RNN + lane * 4] = c4;

    float p[OUT_SZ];
    int i0 = lane * 4;
    #pragma unroll
    for (int j = 0; j < OUT_SZ; j++) {
        p[j] = h4.x * W_out[(i0 + 0) * OUT_SZ + j]
             + h4.y * W_out[(i0 + 1) * OUT_SZ + j]
             + h4.z * W_out[(i0 + 2) * OUT_SZ + j]
             + h4.w * W_out[(i0 + 3) * OUT_SZ + j];
    }
    #pragma unroll
    for (int off = 16; off > 0; off >>= 1) {
        #pragma unroll
        for (int j = 0; j < OUT_SZ; j++)
            p[j] += __shfl_down_sync(0xffffffffu, p[j], off);
    }
    if (lane == 0) {
        #pragma unroll
        for (int j = 0; j < OUT_SZ; j++)
            outputs[((size_t)t * N_NODES + n) * OUT_SZ + j] = p[j] + b_out[j];
    }
}

// ======================= launcher =======================
extern "C" void kernel_launch(void* const* d_in, const int* in_sizes, int n_in,
                              void* d_out, int out_size)
{
    const float* input_data = (const float*)d_in[0];
    const float* grids      = (const float*)d_in[1];
    const float* h0         = (const float*)d_in[2];
    const float* c0         = (const float*)d_in[3];
    const int*   active_idx = (const int*)  d_in[4];
    const float* W_in       = (const float*)d_in[5];
    const float* b_in       = (const float*)d_in[6];
    const float* W_obs      = (const float*)d_in[7];
    const float* b_obs      = (const float*)d_in[8];
    const float* W_ih       = (const float*)d_in[9];
    const float* b_ih       = (const float*)d_in[10];
    const float* W_hh       = (const float*)d_in[11];
    const float* b_hh       = (const float*)d_in[12];
    const float* W_out      = (const float*)d_in[13];
    const float* b_out      = (const float*)d_in[14];

    float* out     = (float*)d_out;
    float* outputs = out;
    float* h_all   = out + (size_t)T_STEPS * N_NODES * OUT_SZ;
    float* c_all   = h_all + (size_t)N_NODES * RNN;

    init_weights_kernel<<<512, 256>>>(W_ih, b_ih, W_hh, b_hh);
    init_state_kernel<<<1024, 256>>>(out, h0, c0);

    for (int t = 0; t < T_STEPS; t++) {
        embed_kernel<<<(K_ACT + 7) / 8, 256>>>(input_data, grids, active_idx,
                                               W_in, b_in, W_obs, b_obs, h_all, c_all, t);
        gemm_kernel<<<dim3(M_TILES, 4), 256>>>();
        scatter_kernel<<<(K_ACT + 7) / 8, 256>>>(active_idx, W_out, b_out,
                                                 outputs, h_all, c_all, t);
    }
}